// round 14
// baseline (speedup 1.0000x reference)
#include <cuda_runtime.h>
#include <cuda_fp16.h>
#include <stdint.h>

#define NB 4096
#define ND 256
#define NM 60
#define TILE 64
#define NT (NB / TILE)              // 64
#define NPAIR (NT * (NT + 1) / 2)   // 2080
#define RSTRIDE 40                  // smem row stride in words (8 mod 32 => LDS.64 conflict-free)

// Device scratch (allocation-free). uint4-typed => 16B alignment.
__device__ uint4    g_norm4[NB * ND * 2 / 16]; // fp16 normalized reps [NB][ND]
__device__ uint4    g_mask[NB];
__device__ int      g_cnt[NB];                 // 3*count
__device__ float4   g_part4[NPAIR];
__device__ unsigned g_ctr;                     // zero-init; reset by last block

// ---------------------------------------------------------------------------
// fexp10(a) = exp(10*a), FMA-only (proven R13, bit-identical lineage).
// ---------------------------------------------------------------------------
__device__ __forceinline__ float fexp10(float a) {
    const float S     = 14.426950408889634f;     // 10 * log2(e)
    const float MAGIC = 12582912.0f;             // 1.5 * 2^23
    float t  = a * S;
    float r  = fmaf(a, S, MAGIC);
    int   ei = __float_as_int(r) - 0x4B400000;
    float f  = t - (r - MAGIC);                  // f in [-0.5, 0.5]
    float p  = fmaf(f, fmaf(f, fmaf(f, fmaf(f, fmaf(f,
                 fmaf(f, 1.5403530e-4f, 1.3333558e-3f),
                 9.6181291e-3f), 5.5504109e-2f), 2.4022651e-1f),
                 6.9314718e-1f), 1.0f);
    return __int_as_float(__float_as_int(p) + (ei << 23));
}

// ---------------------------------------------------------------------------
// Prep (UNCHANGED from R13, proven): warp-per-row normalize + mask (3*cnt).
// ---------------------------------------------------------------------------
__global__ void __launch_bounds__(256) k_prep(const float* __restrict__ rep,
                                              const long long* __restrict__ codes) {
    int w    = threadIdx.x >> 5;
    int lane = threadIdx.x & 31;
    int row  = blockIdx.x * 8 + w;
    if (blockIdx.x == 0 && threadIdx.x == 0) g_ctr = 0u;   // guard reset

    const float4* rp = reinterpret_cast<const float4*>(rep + (size_t)row * ND);
    float4 x0 = rp[lane * 2];
    float4 x1 = rp[lane * 2 + 1];
    float ss = x0.x * x0.x + x0.y * x0.y + x0.z * x0.z + x0.w * x0.w
             + x1.x * x1.x + x1.y * x1.y + x1.z * x1.z + x1.w * x1.w;
    #pragma unroll
    for (int o = 16; o; o >>= 1) ss += __shfl_xor_sync(0xffffffffu, ss, o);
    float inv = rsqrtf(ss);

    __half2 h[4];
    h[0] = __floats2half2_rn(x0.x * inv, x0.y * inv);
    h[1] = __floats2half2_rn(x0.z * inv, x0.w * inv);
    h[2] = __floats2half2_rn(x1.x * inv, x1.y * inv);
    h[3] = __floats2half2_rn(x1.z * inv, x1.w * inv);
    g_norm4[(size_t)row * 32 + lane] = *reinterpret_cast<uint4*>(h);

    const long long* mc = codes + (size_t)row * NM;
    uint32_t m0 = 0, m1 = 0, m2 = 0, m3 = 0;
    {
        int c = (int)mc[lane];
        uint32_t b = 1u << (c & 31);
        int wd = c >> 5;
        if      (wd == 0) m0 |= b;
        else if (wd == 1) m1 |= b;
        else if (wd == 2) m2 |= b;
        else              m3 |= b;
    }
    if (lane < NM - 32) {
        int c = (int)mc[32 + lane];
        uint32_t b = 1u << (c & 31);
        int wd = c >> 5;
        if      (wd == 0) m0 |= b;
        else if (wd == 1) m1 |= b;
        else if (wd == 2) m2 |= b;
        else              m3 |= b;
    }
    #pragma unroll
    for (int o = 16; o; o >>= 1) {
        m0 |= __shfl_xor_sync(0xffffffffu, m0, o);
        m1 |= __shfl_xor_sync(0xffffffffu, m1, o);
        m2 |= __shfl_xor_sync(0xffffffffu, m2, o);
        m3 |= __shfl_xor_sync(0xffffffffu, m3, o);
    }
    if (lane == 0) {
        g_mask[row] = make_uint4(m0, m1, m2, m3);
        g_cnt[row]  = 3 * (__popc(m0) + __popc(m1) + __popc(m2) + __popc(m3));
    }
}

// ---------------------------------------------------------------------------
// mma (f16 in, f32 acc); consistent k-permutation of word pairs (proven).
// ---------------------------------------------------------------------------
#define MMA4X(D, A0, A1, A2, A3, B0, B1)                                     \
    asm volatile("mma.sync.aligned.m16n8k16.row.col.f32.f16.f16.f32 "        \
                 "{%0,%1,%2,%3},{%4,%5,%6,%7},{%8,%9},{%0,%1,%2,%3};\n"      \
                 : "+f"((D)[0]), "+f"((D)[1]), "+f"((D)[2]), "+f"((D)[3])    \
                 : "r"(A0), "r"(A1), "r"(A2), "r"(A3), "r"(B0), "r"(B1))

// Jaccard: 13*inter > 3cA + 3cB (exact; C3A/C3B precomputed 3*count).
#define PROC(ACC, MA, C3A, MB, C3B, EQ) do {                                 \
    int inter = __popc((MA).x & (MB).x) + __popc((MA).y & (MB).y) +          \
                __popc((MA).z & (MB).z) + __popc((MA).w & (MB).w);           \
    bool pos = (13 * inter > (C3A) + (C3B)) && !(EQ);                        \
    float e = fexp10(ACC);                                                   \
    if (pos) { scnt++; sps += (ACC); spe += e; } else { sneg += e; }         \
} while (0)

// ---------------------------------------------------------------------------
// Main pass: one block per upper-tri 64x64 tile pair. 128 threads, 4 warps
// as 2(M)x2(N), warp tile 32x32 (acc=32 regs => 6 blocks = 24 warps/SM).
// LDS.64 fragments; fused last-block final reduction.
// ---------------------------------------------------------------------------
__global__ void __launch_bounds__(128, 6) k_pair(float* __restrict__ out) {
    __shared__ uint32_t sA[TILE * RSTRIDE];   // 10240 B
    __shared__ uint32_t sB[TILE * RSTRIDE];   // 10240 B
    __shared__ uint4 smMA[TILE], smMB[TILE];
    __shared__ int   scA[TILE], scB[TILE];    // 3*count
    __shared__ float red[16];
    __shared__ double sdd[16];
    __shared__ int   flag;

    int tid = threadIdx.x;

    // decode blockIdx -> (ti, tj), ti <= tj
    int p = blockIdx.x, ti = 0;
    while (p >= NT - ti) { p -= NT - ti; ti++; }
    int tj = ti + p;
    int i0 = ti * TILE, j0 = tj * TILE;
    bool diag = (ti == tj);

    if (tid < TILE) { smMA[tid] = g_mask[i0 + tid]; scA[tid] = g_cnt[i0 + tid]; }
    else { int q = tid - TILE; smMB[q] = g_mask[j0 + q]; scB[q] = g_cnt[j0 + q]; }

    int lane = tid & 31, w = tid >> 5;
    int wm = w & 1, wn = w >> 1;                 // warp grid: 2(M) x 2(N)
    int g = lane >> 2, tg = lane & 3;

    float acc[32];
    #pragma unroll
    for (int i = 0; i < 32; i++) acc[i] = 0.0f;

    // K = 256 elems = 4 chunks of 64 elems (8 uint4 per row per chunk)
    #pragma unroll 1
    for (int kc = 0; kc < 4; kc++) {
        __syncthreads();                         // previous compute done (and masks on kc==0)
        #pragma unroll
        for (int r = 0; r < 4; r++) {            // A tile: 64 rows x 8 segs = 512
            int idx = tid + r * 128;
            int row = idx >> 3, seg = idx & 7;
            uint4 v = g_norm4[(size_t)(i0 + row) * 32 + kc * 8 + seg];
            *reinterpret_cast<uint4*>(&sA[row * RSTRIDE + seg * 4]) = v;
        }
        #pragma unroll
        for (int r = 0; r < 4; r++) {            // B tile
            int idx = tid + r * 128;
            int row = idx >> 3, seg = idx & 7;
            uint4 v = g_norm4[(size_t)(j0 + row) * 32 + kc * 8 + seg];
            *reinterpret_cast<uint4*>(&sB[row * RSTRIDE + seg * 4]) = v;
        }
        __syncthreads();

        #pragma unroll
        for (int kk = 0; kk < 4; kk++) {         // 4 k16 slices per chunk
            int ko = kk * 8 + 2 * tg;            // paired 64-bit word offset
            uint2 a0p[2], a1p[2];                // [mi]: rows g / g+8 pairs
            #pragma unroll
            for (int mi = 0; mi < 2; mi++) {
                int rb = (wm * 32 + mi * 16 + g) * RSTRIDE + ko;
                a0p[mi] = *reinterpret_cast<uint2*>(&sA[rb]);
                a1p[mi] = *reinterpret_cast<uint2*>(&sA[rb + 8 * RSTRIDE]);
            }
            #pragma unroll
            for (int nt = 0; nt < 4; nt++) {
                int rb = (wn * 32 + nt * 8 + g) * RSTRIDE + ko;
                uint2 b = *reinterpret_cast<uint2*>(&sB[rb]);
                MMA4X(acc + nt * 4,      a0p[0].x, a1p[0].x, a0p[0].y, a1p[0].y, b.x, b.y);
                MMA4X(acc + 16 + nt * 4, a0p[1].x, a1p[1].x, a0p[1].y, a1p[1].y, b.x, b.y);
            }
        }
    }

    // ---- epilogue: 32 pairs per thread ----
    float sneg = 0.0f, spe = 0.0f, sps = 0.0f;
    int scnt = 0;

    #pragma unroll
    for (int mi = 0; mi < 2; mi++) {
        int rl0 = wm * 32 + mi * 16 + g;
        uint4 mA0 = smMA[rl0];     int cA0 = scA[rl0];
        uint4 mA1 = smMA[rl0 + 8]; int cA1 = scA[rl0 + 8];
        #pragma unroll
        for (int nt = 0; nt < 4; nt++) {
            int cl = wn * 32 + nt * 8 + tg * 2;
            uint4 mB0 = smMB[cl];     int cB0 = scB[cl];
            uint4 mB1 = smMB[cl + 1]; int cB1 = scB[cl + 1];
            float* A4 = acc + mi * 16 + nt * 4;
            PROC(A4[0], mA0, cA0, mB0, cB0, diag && (rl0 == cl));
            PROC(A4[1], mA0, cA0, mB1, cB1, diag && (rl0 == cl + 1));
            PROC(A4[2], mA1, cA1, mB0, cB0, diag && (rl0 + 8 == cl));
            PROC(A4[3], mA1, cA1, mB1, cB1, diag && (rl0 + 8 == cl + 1));
        }
    }

    // block reduce (deterministic, no atomics in the sums)
    float v0 = sneg, v1 = spe, v2 = sps, v3 = (float)scnt;
    #pragma unroll
    for (int o = 16; o; o >>= 1) {
        v0 += __shfl_xor_sync(0xffffffffu, v0, o);
        v1 += __shfl_xor_sync(0xffffffffu, v1, o);
        v2 += __shfl_xor_sync(0xffffffffu, v2, o);
        v3 += __shfl_xor_sync(0xffffffffu, v3, o);
    }
    if (lane == 0) { red[w * 4 + 0] = v0; red[w * 4 + 1] = v1;
                     red[w * 4 + 2] = v2; red[w * 4 + 3] = v3; }
    __syncthreads();
    if (tid == 0) {
        float n = 0, pe = 0, ps = 0, pc = 0;
        #pragma unroll
        for (int i = 0; i < 4; i++) {
            n += red[i * 4 + 0]; pe += red[i * 4 + 1];
            ps += red[i * 4 + 2]; pc += red[i * 4 + 3];
        }
        float f = diag ? 1.0f : 2.0f;   // off-diag tiles stand for (i,j) and (j,i)
        // ps accumulated raw acc values; rescale by temperature (x10) here.
        g_part4[blockIdx.x] = make_float4(n * f, pe * f, ps * 10.0f * f, pc * f);
        __threadfence();                 // publish partial before counting
        unsigned v = atomicAdd(&g_ctr, 1u);
        flag = (v == NPAIR - 1) ? 1 : 0;
    }
    __syncthreads();
    if (!flag) return;

    // ---- last block: deterministic double-precision final reduction ----
    __threadfence();                     // order reads after the atomic
    if (tid == 0) g_ctr = 0u;            // reset for next graph replay
    double n = 0, pe = 0, ps = 0, pc = 0;
    for (int q = tid; q < NPAIR; q += 128) {
        float4 v = __ldcg(&g_part4[q]);
        n += (double)v.x; pe += (double)v.y;
        ps += (double)v.z; pc += (double)v.w;
    }
    #pragma unroll
    for (int o = 16; o; o >>= 1) {
        n  += __shfl_xor_sync(0xffffffffu, n,  o);
        pe += __shfl_xor_sync(0xffffffffu, pe, o);
        ps += __shfl_xor_sync(0xffffffffu, ps, o);
        pc += __shfl_xor_sync(0xffffffffu, pc, o);
    }
    if (lane == 0) { sdd[w * 4 + 0] = n; sdd[w * 4 + 1] = pe;
                     sdd[w * 4 + 2] = ps; sdd[w * 4 + 3] = pc; }
    __syncthreads();
    if (tid == 0) {
        double N = 0, PE = 0, PS = 0, PC = 0;
        #pragma unroll
        for (int i = 0; i < 4; i++) {
            N += sdd[i * 4 + 0]; PE += sdd[i * 4 + 1];
            PS += sdd[i * 4 + 2]; PC += sdd[i * 4 + 3];
        }
        double loss = 0.0;
        if (PC > 0.0) loss = log(N) + PE / (N * PC) - PS / PC;
        out[0] = (float)loss;
    }
}

extern "C" void kernel_launch(void* const* d_in, const int* in_sizes, int n_in,
                              void* d_out, int out_size) {
    (void)in_sizes; (void)n_in; (void)out_size;
    const float*     rep   = (const float*)d_in[0];
    const long long* codes = (const long long*)d_in[1];
    // d_in[2] = labels: unused by the reference loss

    k_prep<<<NB / 8, 256>>>(rep, codes);
    k_pair<<<NPAIR, 128>>>((float*)d_out);
}

// round 15
// speedup vs baseline: 1.0537x; 1.0537x over previous
#include <cuda_runtime.h>
#include <cuda_fp16.h>
#include <stdint.h>

#define NB 4096
#define ND 256
#define NM 60
#define TILE 128
#define NT (NB / TILE)              // 32
#define NPAIR (NT * (NT + 1) / 2)   // 528
#define RSTRIDE 40                  // smem row stride in words (8 mod 32 => LDS.64 conflict-free)

// Device scratch (allocation-free). uint4-typed => 16B alignment.
__device__ uint4    g_norm4[NB * ND * 2 / 16]; // fp16 normalized reps [NB][ND]
__device__ uint4    g_mask[NB];
__device__ int      g_cnt[NB];                 // 3*count
__device__ float4   g_part4[NPAIR];
__device__ unsigned g_ctr;                     // zero-init; reset by last block

// ---------------------------------------------------------------------------
// fexp10(a) = exp(10*a), FMA-only (proven bit-stable lineage).
// ---------------------------------------------------------------------------
__device__ __forceinline__ float fexp10(float a) {
    const float S     = 14.426950408889634f;     // 10 * log2(e)
    const float MAGIC = 12582912.0f;             // 1.5 * 2^23
    float t  = a * S;
    float r  = fmaf(a, S, MAGIC);
    int   ei = __float_as_int(r) - 0x4B400000;
    float f  = t - (r - MAGIC);                  // f in [-0.5, 0.5]
    float p  = fmaf(f, fmaf(f, fmaf(f, fmaf(f, fmaf(f,
                 fmaf(f, 1.5403530e-4f, 1.3333558e-3f),
                 9.6181291e-3f), 5.5504109e-2f), 2.4022651e-1f),
                 6.9314718e-1f), 1.0f);
    return __int_as_float(__float_as_int(p) + (ei << 23));
}

// ---------------------------------------------------------------------------
// Prep (UNCHANGED, proven): warp-per-row normalize + mask (3*cnt).
// ---------------------------------------------------------------------------
__global__ void __launch_bounds__(256) k_prep(const float* __restrict__ rep,
                                              const long long* __restrict__ codes) {
    int w    = threadIdx.x >> 5;
    int lane = threadIdx.x & 31;
    int row  = blockIdx.x * 8 + w;
    if (blockIdx.x == 0 && threadIdx.x == 0) g_ctr = 0u;   // guard reset

    const float4* rp = reinterpret_cast<const float4*>(rep + (size_t)row * ND);
    float4 x0 = rp[lane * 2];
    float4 x1 = rp[lane * 2 + 1];
    float ss = x0.x * x0.x + x0.y * x0.y + x0.z * x0.z + x0.w * x0.w
             + x1.x * x1.x + x1.y * x1.y + x1.z * x1.z + x1.w * x1.w;
    #pragma unroll
    for (int o = 16; o; o >>= 1) ss += __shfl_xor_sync(0xffffffffu, ss, o);
    float inv = rsqrtf(ss);

    __half2 h[4];
    h[0] = __floats2half2_rn(x0.x * inv, x0.y * inv);
    h[1] = __floats2half2_rn(x0.z * inv, x0.w * inv);
    h[2] = __floats2half2_rn(x1.x * inv, x1.y * inv);
    h[3] = __floats2half2_rn(x1.z * inv, x1.w * inv);
    g_norm4[(size_t)row * 32 + lane] = *reinterpret_cast<uint4*>(h);

    const long long* mc = codes + (size_t)row * NM;
    uint32_t m0 = 0, m1 = 0, m2 = 0, m3 = 0;
    {
        int c = (int)mc[lane];
        uint32_t b = 1u << (c & 31);
        int wd = c >> 5;
        if      (wd == 0) m0 |= b;
        else if (wd == 1) m1 |= b;
        else if (wd == 2) m2 |= b;
        else              m3 |= b;
    }
    if (lane < NM - 32) {
        int c = (int)mc[32 + lane];
        uint32_t b = 1u << (c & 31);
        int wd = c >> 5;
        if      (wd == 0) m0 |= b;
        else if (wd == 1) m1 |= b;
        else if (wd == 2) m2 |= b;
        else              m3 |= b;
    }
    #pragma unroll
    for (int o = 16; o; o >>= 1) {
        m0 |= __shfl_xor_sync(0xffffffffu, m0, o);
        m1 |= __shfl_xor_sync(0xffffffffu, m1, o);
        m2 |= __shfl_xor_sync(0xffffffffu, m2, o);
        m3 |= __shfl_xor_sync(0xffffffffu, m3, o);
    }
    if (lane == 0) {
        g_mask[row] = make_uint4(m0, m1, m2, m3);
        g_cnt[row]  = 3 * (__popc(m0) + __popc(m1) + __popc(m2) + __popc(m3));
    }
}

// ---------------------------------------------------------------------------
// mma (f16 in, f32 acc); consistent k-permutation of word pairs (proven).
// ---------------------------------------------------------------------------
#define MMA4X(D, A0, A1, A2, A3, B0, B1)                                     \
    asm volatile("mma.sync.aligned.m16n8k16.row.col.f32.f16.f16.f32 "        \
                 "{%0,%1,%2,%3},{%4,%5,%6,%7},{%8,%9},{%0,%1,%2,%3};\n"      \
                 : "+f"((D)[0]), "+f"((D)[1]), "+f"((D)[2]), "+f"((D)[3])    \
                 : "r"(A0), "r"(A1), "r"(A2), "r"(A3), "r"(B0), "r"(B1))

// Jaccard: 13*inter > 3cA + 3cB (exact; C3A/C3B precomputed 3*count).
#define PROC(ACC, MA, C3A, MB, C3B, EQ) do {                                 \
    int inter = __popc((MA).x & (MB).x) + __popc((MA).y & (MB).y) +          \
                __popc((MA).z & (MB).z) + __popc((MA).w & (MB).w);           \
    bool pos = (13 * inter > (C3A) + (C3B)) && !(EQ);                        \
    float e = fexp10(ACC);                                                   \
    if (pos) { scnt++; sps += (ACC); spe += e; } else { sneg += e; }         \
} while (0)

// ---------------------------------------------------------------------------
// Main pass: one block per upper-tri 128x128 tile pair. 512 threads,
// 16 warps as 4(M)x4(N), warp tile 32x32 => acc = 32 regs/thread.
// TILE-128 traffic economics + 32 warps/SM at launch_bounds(512,2).
// LDS.64 fragments; fused last-block final reduction.
// ---------------------------------------------------------------------------
__global__ void __launch_bounds__(512, 2) k_pair(float* __restrict__ out) {
    __shared__ uint32_t sA[TILE * RSTRIDE];   // 20480 B
    __shared__ uint32_t sB[TILE * RSTRIDE];   // 20480 B
    __shared__ uint4 smMA[TILE], smMB[TILE];
    __shared__ int   scA[TILE], scB[TILE];    // 3*count
    __shared__ float red[64];
    __shared__ double sdd[64];
    __shared__ int   flag;

    int tid = threadIdx.x;

    // decode blockIdx -> (ti, tj), ti <= tj
    int p = blockIdx.x, ti = 0;
    while (p >= NT - ti) { p -= NT - ti; ti++; }
    int tj = ti + p;
    int i0 = ti * TILE, j0 = tj * TILE;
    bool diag = (ti == tj);

    if (tid < TILE) { smMA[tid] = g_mask[i0 + tid]; scA[tid] = g_cnt[i0 + tid]; }
    else if (tid < 2 * TILE) { int q = tid - TILE; smMB[q] = g_mask[j0 + q]; scB[q] = g_cnt[j0 + q]; }

    int lane = tid & 31, w = tid >> 5;
    int wm = w & 3, wn = w >> 2;                 // warp grid: 4(M) x 4(N)
    int g = lane >> 2, tg = lane & 3;

    float acc[32];
    #pragma unroll
    for (int i = 0; i < 32; i++) acc[i] = 0.0f;

    // K = 256 elems = 4 chunks of 64 elems (8 uint4 per row per chunk)
    #pragma unroll 1
    for (int kc = 0; kc < 4; kc++) {
        __syncthreads();                         // previous compute done (and masks on kc==0)
        {                                        // A tile: 1024 uint4, 512 threads x 2
            int idx = tid;
            int row = idx >> 3, seg = idx & 7;
            uint4 v = g_norm4[(size_t)(i0 + row) * 32 + kc * 8 + seg];
            *reinterpret_cast<uint4*>(&sA[row * RSTRIDE + seg * 4]) = v;
            idx = tid + 512; row = idx >> 3; seg = idx & 7;
            v = g_norm4[(size_t)(i0 + row) * 32 + kc * 8 + seg];
            *reinterpret_cast<uint4*>(&sA[row * RSTRIDE + seg * 4]) = v;
        }
        {                                        // B tile
            int idx = tid;
            int row = idx >> 3, seg = idx & 7;
            uint4 v = g_norm4[(size_t)(j0 + row) * 32 + kc * 8 + seg];
            *reinterpret_cast<uint4*>(&sB[row * RSTRIDE + seg * 4]) = v;
            idx = tid + 512; row = idx >> 3; seg = idx & 7;
            v = g_norm4[(size_t)(j0 + row) * 32 + kc * 8 + seg];
            *reinterpret_cast<uint4*>(&sB[row * RSTRIDE + seg * 4]) = v;
        }
        __syncthreads();

        #pragma unroll
        for (int kk = 0; kk < 4; kk++) {         // 4 k16 slices per chunk
            int ko = kk * 8 + 2 * tg;            // paired 64-bit word offset
            uint2 a0p[2], a1p[2];                // [mi]: rows g / g+8 pairs
            #pragma unroll
            for (int mi = 0; mi < 2; mi++) {
                int rb = (wm * 32 + mi * 16 + g) * RSTRIDE + ko;
                a0p[mi] = *reinterpret_cast<uint2*>(&sA[rb]);
                a1p[mi] = *reinterpret_cast<uint2*>(&sA[rb + 8 * RSTRIDE]);
            }
            #pragma unroll
            for (int nt = 0; nt < 4; nt++) {
                int rb = (wn * 32 + nt * 8 + g) * RSTRIDE + ko;
                uint2 b = *reinterpret_cast<uint2*>(&sB[rb]);
                MMA4X(acc + nt * 4,      a0p[0].x, a1p[0].x, a0p[0].y, a1p[0].y, b.x, b.y);
                MMA4X(acc + 16 + nt * 4, a0p[1].x, a1p[1].x, a0p[1].y, a1p[1].y, b.x, b.y);
            }
        }
    }

    // ---- epilogue: 32 pairs per thread ----
    float sneg = 0.0f, spe = 0.0f, sps = 0.0f;
    int scnt = 0;

    #pragma unroll
    for (int mi = 0; mi < 2; mi++) {
        int rl0 = wm * 32 + mi * 16 + g;
        uint4 mA0 = smMA[rl0];     int cA0 = scA[rl0];
        uint4 mA1 = smMA[rl0 + 8]; int cA1 = scA[rl0 + 8];
        #pragma unroll
        for (int nt = 0; nt < 4; nt++) {
            int cl = wn * 32 + nt * 8 + tg * 2;
            uint4 mB0 = smMB[cl];     int cB0 = scB[cl];
            uint4 mB1 = smMB[cl + 1]; int cB1 = scB[cl + 1];
            float* A4 = acc + mi * 16 + nt * 4;
            PROC(A4[0], mA0, cA0, mB0, cB0, diag && (rl0 == cl));
            PROC(A4[1], mA0, cA0, mB1, cB1, diag && (rl0 == cl + 1));
            PROC(A4[2], mA1, cA1, mB0, cB0, diag && (rl0 + 8 == cl));
            PROC(A4[3], mA1, cA1, mB1, cB1, diag && (rl0 + 8 == cl + 1));
        }
    }

    // block reduce (deterministic, no atomics in the sums)
    float v0 = sneg, v1 = spe, v2 = sps, v3 = (float)scnt;
    #pragma unroll
    for (int o = 16; o; o >>= 1) {
        v0 += __shfl_xor_sync(0xffffffffu, v0, o);
        v1 += __shfl_xor_sync(0xffffffffu, v1, o);
        v2 += __shfl_xor_sync(0xffffffffu, v2, o);
        v3 += __shfl_xor_sync(0xffffffffu, v3, o);
    }
    if (lane == 0) { red[w * 4 + 0] = v0; red[w * 4 + 1] = v1;
                     red[w * 4 + 2] = v2; red[w * 4 + 3] = v3; }
    __syncthreads();
    if (tid == 0) {
        float n = 0, pe = 0, ps = 0, pc = 0;
        #pragma unroll
        for (int i = 0; i < 16; i++) {
            n += red[i * 4 + 0]; pe += red[i * 4 + 1];
            ps += red[i * 4 + 2]; pc += red[i * 4 + 3];
        }
        float f = diag ? 1.0f : 2.0f;   // off-diag tiles stand for (i,j) and (j,i)
        // ps accumulated raw acc values; rescale by temperature (x10) here.
        g_part4[blockIdx.x] = make_float4(n * f, pe * f, ps * 10.0f * f, pc * f);
        __threadfence();                 // publish partial before counting
        unsigned v = atomicAdd(&g_ctr, 1u);
        flag = (v == NPAIR - 1) ? 1 : 0;
    }
    __syncthreads();
    if (!flag) return;

    // ---- last block: deterministic double-precision final reduction ----
    __threadfence();                     // order reads after the atomic
    if (tid == 0) g_ctr = 0u;            // reset for next graph replay
    double n = 0, pe = 0, ps = 0, pc = 0;
    for (int q = tid; q < NPAIR; q += 512) {
        float4 v = __ldcg(&g_part4[q]);
        n += (double)v.x; pe += (double)v.y;
        ps += (double)v.z; pc += (double)v.w;
    }
    #pragma unroll
    for (int o = 16; o; o >>= 1) {
        n  += __shfl_xor_sync(0xffffffffu, n,  o);
        pe += __shfl_xor_sync(0xffffffffu, pe, o);
        ps += __shfl_xor_sync(0xffffffffu, ps, o);
        pc += __shfl_xor_sync(0xffffffffu, pc, o);
    }
    if (lane == 0) { sdd[w * 4 + 0] = n; sdd[w * 4 + 1] = pe;
                     sdd[w * 4 + 2] = ps; sdd[w * 4 + 3] = pc; }
    __syncthreads();
    if (tid == 0) {
        double N = 0, PE = 0, PS = 0, PC = 0;
        #pragma unroll
        for (int i = 0; i < 16; i++) {
            N += sdd[i * 4 + 0]; PE += sdd[i * 4 + 1];
            PS += sdd[i * 4 + 2]; PC += sdd[i * 4 + 3];
        }
        double loss = 0.0;
        if (PC > 0.0) loss = log(N) + PE / (N * PC) - PS / PC;
        out[0] = (float)loss;
    }
}

extern "C" void kernel_launch(void* const* d_in, const int* in_sizes, int n_in,
                              void* d_out, int out_size) {
    (void)in_sizes; (void)n_in; (void)out_size;
    const float*     rep   = (const float*)d_in[0];
    const long long* codes = (const long long*)d_in[1];
    // d_in[2] = labels: unused by the reference loss

    k_prep<<<NB / 8, 256>>>(rep, codes);
    k_pair<<<NPAIR, 512>>>((float*)d_out);
}

// round 16
// speedup vs baseline: 1.2937x; 1.2278x over previous
#include <cuda_runtime.h>
#include <cuda_fp16.h>
#include <stdint.h>

#define NB 4096
#define ND 256
#define NM 60
#define TILE 128
#define NT (NB / TILE)              // 32
#define NPAIR (NT * (NT + 1) / 2)   // 528
#define ST 20                       // smem row stride in words (16 data + 4 pad)

// Device scratch (allocation-free). uint4-typed => 16B alignment.
// g_norm4 layout: CHUNK-MAJOR [chunk32(8)][row(4096)][seg(4)] uint4 —
// one K-chunk of one row-tile is 8KB contiguous.
__device__ uint4    g_norm4[8 * NB * 4];
__device__ uint4    g_mask[NB];
__device__ int      g_cnt[NB];                 // 3*count
__device__ float4   g_part4[NPAIR];
__device__ unsigned g_ctr;                     // zero-init; reset by last block

// ---------------------------------------------------------------------------
// fexp10(a) = exp(10*a), FMA-only (proven bit-stable lineage).
// ---------------------------------------------------------------------------
__device__ __forceinline__ float fexp10(float a) {
    const float S     = 14.426950408889634f;     // 10 * log2(e)
    const float MAGIC = 12582912.0f;             // 1.5 * 2^23
    float t  = a * S;
    float r  = fmaf(a, S, MAGIC);
    int   ei = __float_as_int(r) - 0x4B400000;
    float f  = t - (r - MAGIC);                  // f in [-0.5, 0.5]
    float p  = fmaf(f, fmaf(f, fmaf(f, fmaf(f, fmaf(f,
                 fmaf(f, 1.5403530e-4f, 1.3333558e-3f),
                 9.6181291e-3f), 5.5504109e-2f), 2.4022651e-1f),
                 6.9314718e-1f), 1.0f);
    return __int_as_float(__float_as_int(p) + (ei << 23));
}

// ---------------------------------------------------------------------------
// Prep: warp-per-row (proven). Only change: chunk-major g_norm4 layout.
// Lane l's uint4 = elements 8l..8l+7 of the row = chunk (l>>2), seg (l&3).
// ---------------------------------------------------------------------------
__global__ void __launch_bounds__(256) k_prep(const float* __restrict__ rep,
                                              const long long* __restrict__ codes) {
    int w    = threadIdx.x >> 5;
    int lane = threadIdx.x & 31;
    int row  = blockIdx.x * 8 + w;
    if (blockIdx.x == 0 && threadIdx.x == 0) g_ctr = 0u;   // guard reset

    const float4* rp = reinterpret_cast<const float4*>(rep + (size_t)row * ND);
    float4 x0 = rp[lane * 2];
    float4 x1 = rp[lane * 2 + 1];
    float ss = x0.x * x0.x + x0.y * x0.y + x0.z * x0.z + x0.w * x0.w
             + x1.x * x1.x + x1.y * x1.y + x1.z * x1.z + x1.w * x1.w;
    #pragma unroll
    for (int o = 16; o; o >>= 1) ss += __shfl_xor_sync(0xffffffffu, ss, o);
    float inv = rsqrtf(ss);

    __half2 h[4];
    h[0] = __floats2half2_rn(x0.x * inv, x0.y * inv);
    h[1] = __floats2half2_rn(x0.z * inv, x0.w * inv);
    h[2] = __floats2half2_rn(x1.x * inv, x1.y * inv);
    h[3] = __floats2half2_rn(x1.z * inv, x1.w * inv);
    g_norm4[((lane >> 2) * NB + row) * 4 + (lane & 3)] = *reinterpret_cast<uint4*>(h);

    const long long* mc = codes + (size_t)row * NM;
    uint32_t m0 = 0, m1 = 0, m2 = 0, m3 = 0;
    {
        int c = (int)mc[lane];
        uint32_t b = 1u << (c & 31);
        int wd = c >> 5;
        if      (wd == 0) m0 |= b;
        else if (wd == 1) m1 |= b;
        else if (wd == 2) m2 |= b;
        else              m3 |= b;
    }
    if (lane < NM - 32) {
        int c = (int)mc[32 + lane];
        uint32_t b = 1u << (c & 31);
        int wd = c >> 5;
        if      (wd == 0) m0 |= b;
        else if (wd == 1) m1 |= b;
        else if (wd == 2) m2 |= b;
        else              m3 |= b;
    }
    #pragma unroll
    for (int o = 16; o; o >>= 1) {
        m0 |= __shfl_xor_sync(0xffffffffu, m0, o);
        m1 |= __shfl_xor_sync(0xffffffffu, m1, o);
        m2 |= __shfl_xor_sync(0xffffffffu, m2, o);
        m3 |= __shfl_xor_sync(0xffffffffu, m3, o);
    }
    if (lane == 0) {
        g_mask[row] = make_uint4(m0, m1, m2, m3);
        g_cnt[row]  = 3 * (__popc(m0) + __popc(m1) + __popc(m2) + __popc(m3));
    }
}

// ---------------------------------------------------------------------------
// mma (f16 in, f32 acc) — R11's exact instruction/fragment mapping.
// ---------------------------------------------------------------------------
#define MMA4(D, A, B0, B1)                                                   \
    asm volatile("mma.sync.aligned.m16n8k16.row.col.f32.f16.f16.f32 "        \
                 "{%0,%1,%2,%3},{%4,%5,%6,%7},{%8,%9},{%0,%1,%2,%3};\n"      \
                 : "+f"((D)[0]), "+f"((D)[1]), "+f"((D)[2]), "+f"((D)[3])    \
                 : "r"((A)[0]), "r"((A)[1]), "r"((A)[2]), "r"((A)[3]),       \
                   "r"(B0), "r"(B1))

// Jaccard: 13*inter > 3cA + 3cB (exact; C3A/C3B precomputed 3*count).
#define PROC(ACC, MA, C3A, MB, C3B, EQ) do {                                 \
    int inter = __popc((MA).x & (MB).x) + __popc((MA).y & (MB).y) +          \
                __popc((MA).z & (MB).z) + __popc((MA).w & (MB).w);           \
    bool pos = (13 * inter > (C3A) + (C3B)) && !(EQ);                        \
    float e = fexp10(ACC);                                                   \
    if (pos) { scnt++; sps += (ACC); spe += e; } else { sneg += e; }         \
} while (0)

// ---------------------------------------------------------------------------
// Main pass: one block per upper-tri 128x128 tile pair. 256 threads, 8 warps
// as 4(M)x2(N), warp tile 32x64, acc[64] (R11 economics). DOUBLE-BUFFERED
// static smem, K-chunks of 32: one __syncthreads per chunk; STS overlaps
// other warps' MMA; LDG prefetch issued before the barrier.
// ---------------------------------------------------------------------------
__global__ void __launch_bounds__(256, 2) k_pair(float* __restrict__ out) {
    __shared__ uint32_t sA[2][TILE * ST];     // 2 x 10240 B
    __shared__ uint32_t sB[2][TILE * ST];     // 2 x 10240 B
    __shared__ uint4 smMA[TILE], smMB[TILE];
    __shared__ int   scA[TILE], scB[TILE];    // 3*count
    __shared__ float red[32];
    __shared__ double sdd[32];
    __shared__ int   flag;

    int tid = threadIdx.x;

    // decode blockIdx -> (ti, tj), ti <= tj
    int p = blockIdx.x, ti = 0;
    while (p >= NT - ti) { p -= NT - ti; ti++; }
    int tj = ti + p;
    int i0 = ti * TILE, j0 = tj * TILE;
    bool diag = (ti == tj);

    if (tid < TILE) { smMA[tid] = g_mask[i0 + tid]; scA[tid] = g_cnt[i0 + tid]; }
    else { int q = tid - TILE; smMB[q] = g_mask[j0 + q]; scB[q] = g_cnt[j0 + q]; }

    int lane = tid & 31, w = tid >> 5;
    int wm = w & 3, wn = w >> 2;                 // warp grid: 4(M) x 2(N)
    int g = lane >> 2, tg = lane & 3;

    // staging indices: 512 uint4 per tile per chunk; thread does 2 (A) + 2 (B)
    int r0 = tid >> 2, s0 = tid & 3;             // idx = tid
    int r1 = (tid + 256) >> 2, s1 = tid & 3;     // idx = tid + 256

    float acc[64];
    #pragma unroll
    for (int i = 0; i < 64; i++) acc[i] = 0.0f;

    // prologue: load chunk 0 into registers
    uint4 pa0 = g_norm4[(size_t)(i0 + r0) * 4 + s0];
    uint4 pa1 = g_norm4[(size_t)(i0 + r1) * 4 + s1];
    uint4 pb0 = g_norm4[(size_t)(j0 + r0) * 4 + s0];
    uint4 pb1 = g_norm4[(size_t)(j0 + r1) * 4 + s1];

    // K = 256 elems = 8 chunks of 32 elems
    #pragma unroll 1
    for (int kc = 0; kc < 8; kc++) {
        int s = kc & 1;
        // STS current chunk (safe: sync(kc-1) drained MMA(kc-2) on this buffer)
        *reinterpret_cast<uint4*>(&sA[s][r0 * ST + s0 * 4]) = pa0;
        *reinterpret_cast<uint4*>(&sA[s][r1 * ST + s1 * 4]) = pa1;
        *reinterpret_cast<uint4*>(&sB[s][r0 * ST + s0 * 4]) = pb0;
        *reinterpret_cast<uint4*>(&sB[s][r1 * ST + s1 * 4]) = pb1;
        if (kc < 7) {                            // prefetch next chunk (before barrier)
            size_t base = (size_t)(kc + 1) * NB * 4;
            pa0 = g_norm4[base + (size_t)(i0 + r0) * 4 + s0];
            pa1 = g_norm4[base + (size_t)(i0 + r1) * 4 + s1];
            pb0 = g_norm4[base + (size_t)(j0 + r0) * 4 + s0];
            pb1 = g_norm4[base + (size_t)(j0 + r1) * 4 + s1];
        }
        __syncthreads();                         // buffer s fully written

        #pragma unroll
        for (int kk = 0; kk < 2; kk++) {         // 2 k16 slices per chunk
            uint32_t a[2][4];
            #pragma unroll
            for (int mi = 0; mi < 2; mi++) {
                int rb = (wm * 32 + mi * 16 + g) * ST + kk * 8 + tg;
                a[mi][0] = sA[s][rb];
                a[mi][1] = sA[s][rb + 8 * ST];
                a[mi][2] = sA[s][rb + 4];
                a[mi][3] = sA[s][rb + 8 * ST + 4];
            }
            #pragma unroll
            for (int nt = 0; nt < 8; nt++) {
                int rb = (wn * 64 + nt * 8 + g) * ST + kk * 8 + tg;
                uint32_t b0 = sB[s][rb];
                uint32_t b1 = sB[s][rb + 4];
                MMA4(acc + nt * 4,      a[0], b0, b1);
                MMA4(acc + 32 + nt * 4, a[1], b0, b1);
            }
        }
    }

    // ---- epilogue (diag specialization; numerics unchanged) ----
    float sneg = 0.0f, spe = 0.0f, sps = 0.0f;
    int scnt = 0;

    #define EPILOGUE(EQ0, EQ1, EQ2, EQ3)                                      \
        _Pragma("unroll")                                                     \
        for (int mi = 0; mi < 2; mi++) {                                      \
            int rl0 = wm * 32 + mi * 16 + g;                                  \
            uint4 mA0 = smMA[rl0];     int cA0 = scA[rl0];                    \
            uint4 mA1 = smMA[rl0 + 8]; int cA1 = scA[rl0 + 8];                \
            _Pragma("unroll")                                                 \
            for (int nt = 0; nt < 8; nt++) {                                  \
                int cl = wn * 64 + nt * 8 + tg * 2;                           \
                uint4 mB0 = smMB[cl];     int cB0 = scB[cl];                  \
                uint4 mB1 = smMB[cl + 1]; int cB1 = scB[cl + 1];              \
                float* A4 = acc + mi * 32 + nt * 4;                           \
                PROC(A4[0], mA0, cA0, mB0, cB0, EQ0);                         \
                PROC(A4[1], mA0, cA0, mB1, cB1, EQ1);                         \
                PROC(A4[2], mA1, cA1, mB0, cB0, EQ2);                         \
                PROC(A4[3], mA1, cA1, mB1, cB1, EQ3);                         \
            }                                                                 \
        }

    if (diag) {
        EPILOGUE((rl0 == cl), (rl0 == cl + 1), (rl0 + 8 == cl), (rl0 + 8 == cl + 1))
    } else {
        EPILOGUE(false, false, false, false)
    }
    #undef EPILOGUE

    // block reduce (deterministic, no atomics in the sums)
    float v0 = sneg, v1 = spe, v2 = sps, v3 = (float)scnt;
    #pragma unroll
    for (int o = 16; o; o >>= 1) {
        v0 += __shfl_xor_sync(0xffffffffu, v0, o);
        v1 += __shfl_xor_sync(0xffffffffu, v1, o);
        v2 += __shfl_xor_sync(0xffffffffu, v2, o);
        v3 += __shfl_xor_sync(0xffffffffu, v3, o);
    }
    if (lane == 0) { red[w * 4 + 0] = v0; red[w * 4 + 1] = v1;
                     red[w * 4 + 2] = v2; red[w * 4 + 3] = v3; }
    __syncthreads();
    if (tid == 0) {
        float n = 0, pe = 0, ps = 0, pc = 0;
        #pragma unroll
        for (int i = 0; i < 8; i++) {
            n += red[i * 4 + 0]; pe += red[i * 4 + 1];
            ps += red[i * 4 + 2]; pc += red[i * 4 + 3];
        }
        float f = diag ? 1.0f : 2.0f;   // off-diag tiles stand for (i,j) and (j,i)
        // ps accumulated raw acc values; rescale by temperature (x10) here.
        g_part4[blockIdx.x] = make_float4(n * f, pe * f, ps * 10.0f * f, pc * f);
        __threadfence();                 // publish partial before counting
        unsigned v = atomicAdd(&g_ctr, 1u);
        flag = (v == NPAIR - 1) ? 1 : 0;
    }
    __syncthreads();
    if (!flag) return;

    // ---- last block: deterministic double-precision final reduction ----
    __threadfence();                     // order reads after the atomic
    if (tid == 0) g_ctr = 0u;            // reset for next graph replay
    double n = 0, pe = 0, ps = 0, pc = 0;
    for (int q = tid; q < NPAIR; q += 256) {
        float4 v = __ldcg(&g_part4[q]);
        n += (double)v.x; pe += (double)v.y;
        ps += (double)v.z; pc += (double)v.w;
    }
    #pragma unroll
    for (int o = 16; o; o >>= 1) {
        n  += __shfl_xor_sync(0xffffffffu, n,  o);
        pe += __shfl_xor_sync(0xffffffffu, pe, o);
        ps += __shfl_xor_sync(0xffffffffu, ps, o);
        pc += __shfl_xor_sync(0xffffffffu, pc, o);
    }
    if (lane == 0) { sdd[w * 4 + 0] = n; sdd[w * 4 + 1] = pe;
                     sdd[w * 4 + 2] = ps; sdd[w * 4 + 3] = pc; }
    __syncthreads();
    if (tid == 0) {
        double N = 0, PE = 0, PS = 0, PC = 0;
        #pragma unroll
        for (int i = 0; i < 8; i++) {
            N += sdd[i * 4 + 0]; PE += sdd[i * 4 + 1];
            PS += sdd[i * 4 + 2]; PC += sdd[i * 4 + 3];
        }
        double loss = 0.0;
        if (PC > 0.0) loss = log(N) + PE / (N * PC) - PS / PC;
        out[0] = (float)loss;
    }
}

extern "C" void kernel_launch(void* const* d_in, const int* in_sizes, int n_in,
                              void* d_out, int out_size) {
    (void)in_sizes; (void)n_in; (void)out_size;
    const float*     rep   = (const float*)d_in[0];
    const long long* codes = (const long long*)d_in[1];
    // d_in[2] = labels: unused by the reference loss

    k_prep<<<NB / 8, 256>>>(rep, codes);
    k_pair<<<NPAIR, 256>>>((float*)d_out);
}